// round 4
// baseline (speedup 1.0000x reference)
#include <cuda_runtime.h>
#include <cstdint>

// (32, 1024, 2048) fp32.  noisy = data + 0.1*noise; mask top-512 uniforms per row
// (ties at threshold -> lowest index first, matching jax.lax.top_k stability).
// out[0:N) = masked, out[N:2N) = mask_inverse.

#define D_DIM 2048
#define K_SEL 512
#define TPB   256
#define EPT   8          // D_DIM / TPB, contiguous per thread
#define FULLM 0xFFFFFFFFu

__global__ __launch_bounds__(TPB, 4)
void obs_mask_kernel(const float* __restrict__ data,
                     const float* __restrict__ noise,
                     const float* __restrict__ rand_vals,
                     float* __restrict__ out_masked,
                     float* __restrict__ out_inv)
{
    __shared__ unsigned s_hist[256];   // fast path uses [0..63]; fallback uses all 256
    __shared__ unsigned s_cnt[8];
    __shared__ unsigned s_cand[64];
    __shared__ unsigned s_bc[2];       // {selected t16 bin, count strictly above bin}
    __shared__ unsigned s_res[2];      // {T bits, idxT}
    __shared__ unsigned s_n;

    const int tid  = threadIdx.x;
    const int lane = tid & 31;
    const int wid  = tid >> 5;
    const size_t base = (size_t)blockIdx.x * D_DIM;
    const unsigned idxBase = (unsigned)tid << 3;

    // ---- PREFETCH: issue ALL per-thread global loads up front (6 x 16B in flight)
    // so the entire selection phase runs under outstanding DRAM traffic.
    const uint4*  rp = reinterpret_cast<const uint4*>(rand_vals + base) + (tid << 1);
    const float4* dp = reinterpret_cast<const float4*>(data  + base) + (tid << 1);
    const float4* np = reinterpret_cast<const float4*>(noise + base) + (tid << 1);

    uint4  ra = __ldcs(rp);
    uint4  rb = __ldcs(rp + 1);
    float4 d0 = __ldcs(dp);
    float4 d1 = __ldcs(dp + 1);
    float4 n0 = __ldcs(np);
    float4 n1 = __ldcs(np + 1);

    unsigned r[EPT] = {ra.x, ra.y, ra.z, ra.w, rb.x, rb.y, rb.z, rb.w};

    // ---- cheap exact band census: c1 = #{v>=0.75}, c2 = #{v>=0.5}, any >= 1.0 ----
    unsigned cpk = 0;   // c1 in low 16, c2 in high 16
    int big = 0;
    #pragma unroll
    for (int j = 0; j < EPT; ++j) {
        cpk += (r[j] >= 0x3F400000u) ? 1u : 0u;
        cpk += (r[j] >= 0x3F000000u) ? 0x10000u : 0u;
        big |= (r[j] >= 0x3F800000u);
    }
    #pragma unroll
    for (int off = 16; off >= 1; off >>= 1)
        cpk += __shfl_down_sync(FULLM, cpk, off);
    if (lane == 0) s_cnt[wid] = cpk;
    if (tid < 64) s_hist[tid] = 0;
    if (tid == 0) s_n = 0;

    int anyBig = __syncthreads_or(big);          // barrier #1

    unsigned csum = 0;
    #pragma unroll
    for (int w = 0; w < 8; ++w) csum += s_cnt[w];
    const unsigned c1 = csum & 0xFFFFu;
    const unsigned c2 = csum >> 16;

    bool generic = (anyBig != 0);
    unsigned lo16 = 0, remBand = 0;
    if (!generic) {
        if (c1 >= K_SEL)      { lo16 = 0x3F40u; remBand = K_SEL; }
        else if (c2 >= K_SEL) { lo16 = 0x3F00u; remBand = K_SEL - c1; }
        else                  { generic = true; }
    }

    if (!generic) {
        // ---- 64-bin histogram over the quarter-band only (~2 atomics/thread) ----
        #pragma unroll
        for (int j = 0; j < EPT; ++j) {
            unsigned bin = (r[j] >> 16) - lo16;
            if (bin < 64u) atomicAdd(&s_hist[bin], 1u);
        }
        __syncthreads();                         // barrier #2

        // ---- warp0: suffix scan of 64 bins, pick crossing bin ----
        if (wid == 0) {
            uint2 h2 = reinterpret_cast<const uint2*>(s_hist)[lane];  // bins 2l, 2l+1
            unsigned s1 = h2.y;
            unsigned s0 = h2.x + s1;
            unsigned inc = s0;
            #pragma unroll
            for (int off = 1; off < 32; off <<= 1) {
                unsigned o = __shfl_down_sync(FULLM, inc, off);
                if (lane + off < 32) inc += o;
            }
            unsigned abovePairs = inc - s0;
            unsigned S_hi = abovePairs + s1;      // bin 2l+1
            unsigned S_lo = abovePairs + s0;      // bin 2l
            if (S_hi >= remBand && S_hi - h2.y < remBand) {
                s_bc[0] = lo16 + 2u * lane + 1u;  s_bc[1] = S_hi - h2.y;
            }
            if (S_lo >= remBand && S_lo - h2.x < remBand) {
                s_bc[0] = lo16 + 2u * lane;       s_bc[1] = S_lo - h2.x;
            }
        }
        __syncthreads();                         // barrier #3

        const unsigned t16sel = s_bc[0];
        const unsigned rem2   = remBand - s_bc[1];   // rank within crossing bin, >= 1

        // ---- collect crossing-bin candidates as packed keys ----
        #pragma unroll
        for (int j = 0; j < EPT; ++j) {
            if ((r[j] >> 16) == t16sel) {
                unsigned key = ((r[j] & 0xFFFFu) << 11) | (2047u - (idxBase + j));
                unsigned pos = atomicAdd(&s_n, 1u);
                if (pos < 64u) s_cand[pos] = key;
            }
        }
        __syncthreads();                         // barrier #4

        unsigned n = s_n;
        if (n <= 64u) {
            // ---- warp0: exact rank-(rem2) select among n distinct keys ----
            if (wid == 0) {
                unsigned k0 = (lane < (int)n)        ? s_cand[lane]      : 0u;
                unsigned k1 = ((unsigned)lane + 32u < n) ? s_cand[lane + 32] : 0u;
                unsigned r0 = 0, r1 = 0;
                unsigned nn = n < 32u ? n : 32u;
                for (unsigned i = 0; i < nn; ++i) {
                    unsigned b = __shfl_sync(FULLM, k0, i);
                    r0 += (b > k0); r1 += (b > k1);
                }
                if (n > 32u) {
                    unsigned n2 = n - 32u;
                    for (unsigned i = 0; i < n2; ++i) {
                        unsigned b = __shfl_sync(FULLM, k1, i);
                        r0 += (b > k0); r1 += (b > k1);
                    }
                }
                unsigned target = rem2 - 1u;
                if ((unsigned)lane < n && r0 == target) {
                    s_res[0] = (t16sel << 16) | (k0 >> 11);
                    s_res[1] = 2047u - (k0 & 0x7FFu);
                }
                if ((unsigned)lane + 32u < n && r1 == target) {
                    s_res[0] = (t16sel << 16) | (k1 >> 11);
                    s_res[1] = 2047u - (k1 & 0x7FFu);
                }
            }
            __syncthreads();                     // barrier #5
        } else {
            generic = true;                      // block-uniform
        }
    }

    if (generic) {
        // ---- fully generic exact path: 4-pass byte radix + boundary index ----
        __syncthreads();
        unsigned prefix = 0, remG = K_SEL;
        for (int pass = 0; pass < 4; ++pass) {
            const int shift = 24 - 8 * pass;
            const unsigned pmask = (pass == 0) ? 0u : (0xFFFFFFFFu << (shift + 8));
            s_hist[tid] = 0;
            __syncthreads();
            for (int j = 0; j < EPT; ++j)
                if ((r[j] & pmask) == prefix)
                    atomicAdd(&s_hist[(r[j] >> shift) & 255u], 1u);
            __syncthreads();
            unsigned h = s_hist[tid], v = h;
            for (int off = 1; off < 32; off <<= 1) {
                unsigned o = __shfl_down_sync(FULLM, v, off);
                if (lane + off < 32) v += o;
            }
            if (lane == 0) s_cnt[wid] = v;
            __syncthreads();
            unsigned addHi = 0;
            for (int w = 0; w < 8; ++w)
                if (w > wid) addHi += s_cnt[w];
            unsigned S = v + addHi;
            if (S >= remG && S - h < remG) { s_bc[0] = (unsigned)tid; s_bc[1] = S - h; }
            __syncthreads();
            prefix |= s_bc[0] << shift;
            remG   -= s_bc[1];
            __syncthreads();
        }
        // locate idxT: index of the remG-th equal-to-prefix element (ascending index)
        unsigned cnt = 0;
        for (int j = 0; j < EPT; ++j) cnt += (r[j] == prefix) ? 1u : 0u;
        unsigned iv = cnt;
        for (int off = 1; off < 32; off <<= 1) {
            unsigned o = __shfl_up_sync(FULLM, iv, off);
            if (lane >= off) iv += o;
        }
        if (lane == 31) s_cnt[wid] = iv;
        __syncthreads();
        unsigned wOff = 0;
        for (int w = 0; w < 8; ++w)
            if (w < wid) wOff += s_cnt[w];
        unsigned excl = wOff + iv - cnt;
        if (excl < remG && remG <= excl + cnt) {
            unsigned need = remG - excl, run = 0;
            for (int j = 0; j < EPT; ++j)
                if (r[j] == prefix && ++run == need) {
                    s_res[0] = prefix;
                    s_res[1] = idxBase + j;
                }
        }
        __syncthreads();
    }

    const unsigned T    = s_res[0];
    const unsigned idxT = s_res[1];

    // ---- fused mask + dual streaming output from prefetched registers ----
    float4* mp = reinterpret_cast<float4*>(out_masked + base) + (tid << 1);
    float4* ip = reinterpret_cast<float4*>(out_inv    + base) + (tid << 1);

    float dv[8] = {d0.x, d0.y, d0.z, d0.w, d1.x, d1.y, d1.z, d1.w};
    float nv[8] = {n0.x, n0.y, n0.z, n0.w, n1.x, n1.y, n1.z, n1.w};

    float ov[8], gv[8];
    #pragma unroll
    for (int j = 0; j < EPT; ++j) {
        bool masked = (r[j] > T) | ((r[j] == T) & (idxBase + (unsigned)j <= idxT));
        ov[j] = masked ? 0.0f : fmaf(0.1f, nv[j], dv[j]);
        gv[j] = masked ? 0.0f : 1.0f;
    }
    __stcs(mp,     make_float4(ov[0], ov[1], ov[2], ov[3]));
    __stcs(mp + 1, make_float4(ov[4], ov[5], ov[6], ov[7]));
    __stcs(ip,     make_float4(gv[0], gv[1], gv[2], gv[3]));
    __stcs(ip + 1, make_float4(gv[4], gv[5], gv[6], gv[7]));
}

extern "C" void kernel_launch(void* const* d_in, const int* in_sizes, int n_in,
                              void* d_out, int out_size)
{
    const float* data  = (const float*)d_in[0];
    const float* noise = (const float*)d_in[1];
    const float* rv    = (const float*)d_in[2];
    float* out = (float*)d_out;

    size_t n = (size_t)in_sizes[0];   // 32*1024*2048
    int rows = (int)(n / D_DIM);      // 32768

    obs_mask_kernel<<<rows, TPB>>>(data, noise, rv, out, out + n);
}

// round 7
// speedup vs baseline: 1.1005x; 1.1005x over previous
#include <cuda_runtime.h>
#include <cstdint>

// (32, 1024, 2048) fp32.  noisy = data + 0.1*noise; mask top-512 uniforms per row
// (ties at threshold -> lowest index first, matching jax.lax.top_k stability).
// out[0:N) = masked, out[N:2N) = mask_inverse.

#define D_DIM 2048
#define K_SEL 512
#define TPB   256
#define EPT   8          // D_DIM / TPB, contiguous per thread
#define FULLM 0xFFFFFFFFu

#define CP_ASYNC16(dst_u32, src_ptr) \
    asm volatile("cp.async.cg.shared.global [%0], [%1], 16;" :: "r"(dst_u32), "l"(src_ptr) : "memory")

__global__ __launch_bounds__(TPB, 6)
void obs_mask_kernel(const float* __restrict__ data,
                     const float* __restrict__ noise,
                     const float* __restrict__ rand_vals,
                     float* __restrict__ out_masked,
                     float* __restrict__ out_inv)
{
    __shared__ float4   s_dn[1024];    // 16KB: [0,512) = data row, [512,1024) = noise row
    __shared__ unsigned s_hist[256];   // fast path uses [0..63]; fallback uses all 256
    __shared__ unsigned s_cnt[8];
    __shared__ unsigned s_cand[64];
    __shared__ unsigned s_bc[2];       // {selected t16 bin, count strictly above bin}
    __shared__ unsigned s_res[2];      // {T bits, idxT}
    __shared__ unsigned s_n;

    const int tid  = threadIdx.x;
    const int lane = tid & 31;
    const int wid  = tid >> 5;
    const size_t base = (size_t)blockIdx.x * D_DIM;
    const unsigned idxBase = (unsigned)tid << 3;

    // ---- rand loads into registers (needed immediately for selection) ----
    const uint4* rp = reinterpret_cast<const uint4*>(rand_vals + base) + (tid << 1);
    uint4 ra = __ldcs(rp);
    uint4 rb = __ldcs(rp + 1);

    // ---- cp.async prefetch of data+noise into smem: drains during selection,
    //      costs no registers. Each thread copies (and later reads) its own bytes.
    {
        unsigned sbase = (unsigned)__cvta_generic_to_shared(s_dn);
        const float4* dp = reinterpret_cast<const float4*>(data  + base) + (tid << 1);
        const float4* np = reinterpret_cast<const float4*>(noise + base) + (tid << 1);
        unsigned dD = sbase + (unsigned)(tid * 32);            // 2 float4 per thread
        unsigned dN = sbase + 8192u + (unsigned)(tid * 32);
        CP_ASYNC16(dD,       dp);
        CP_ASYNC16(dD + 16u, dp + 1);
        CP_ASYNC16(dN,       np);
        CP_ASYNC16(dN + 16u, np + 1);
        asm volatile("cp.async.commit_group;" ::: "memory");
    }

    unsigned r[EPT] = {ra.x, ra.y, ra.z, ra.w, rb.x, rb.y, rb.z, rb.w};

    // ---- cheap exact band census: c1 = #{v>=0.75}, c2 = #{v>=0.5}, any >= 1.0 ----
    unsigned cpk = 0;   // c1 in low 16, c2 in high 16
    int big = 0;
    #pragma unroll
    for (int j = 0; j < EPT; ++j) {
        cpk += (r[j] >= 0x3F400000u) ? 1u : 0u;
        cpk += (r[j] >= 0x3F000000u) ? 0x10000u : 0u;
        big |= (r[j] >= 0x3F800000u);
    }
    #pragma unroll
    for (int off = 16; off >= 1; off >>= 1)
        cpk += __shfl_down_sync(FULLM, cpk, off);
    if (lane == 0) s_cnt[wid] = cpk;
    if (tid < 64) s_hist[tid] = 0;
    if (tid == 0) s_n = 0;

    int anyBig = __syncthreads_or(big);          // barrier #1

    unsigned csum = 0;
    #pragma unroll
    for (int w = 0; w < 8; ++w) csum += s_cnt[w];
    const unsigned c1 = csum & 0xFFFFu;
    const unsigned c2 = csum >> 16;

    bool generic = (anyBig != 0);
    unsigned lo16 = 0, remBand = 0;
    if (!generic) {
        if (c1 >= K_SEL)      { lo16 = 0x3F40u; remBand = K_SEL; }
        else if (c2 >= K_SEL) { lo16 = 0x3F00u; remBand = K_SEL - c1; }
        else                  { generic = true; }
    }

    if (!generic) {
        // ---- 64-bin histogram over the quarter-band only (~2 atomics/thread) ----
        #pragma unroll
        for (int j = 0; j < EPT; ++j) {
            unsigned bin = (r[j] >> 16) - lo16;
            if (bin < 64u) atomicAdd(&s_hist[bin], 1u);
        }
        __syncthreads();                         // barrier #2

        // ---- warp0: suffix scan of 64 bins, pick crossing bin ----
        if (wid == 0) {
            uint2 h2 = reinterpret_cast<const uint2*>(s_hist)[lane];  // bins 2l, 2l+1
            unsigned s1 = h2.y;
            unsigned s0 = h2.x + s1;
            unsigned inc = s0;
            #pragma unroll
            for (int off = 1; off < 32; off <<= 1) {
                unsigned o = __shfl_down_sync(FULLM, inc, off);
                if (lane + off < 32) inc += o;
            }
            unsigned abovePairs = inc - s0;
            unsigned S_hi = abovePairs + s1;      // bin 2l+1
            unsigned S_lo = abovePairs + s0;      // bin 2l
            if (S_hi >= remBand && S_hi - h2.y < remBand) {
                s_bc[0] = lo16 + 2u * lane + 1u;  s_bc[1] = S_hi - h2.y;
            }
            if (S_lo >= remBand && S_lo - h2.x < remBand) {
                s_bc[0] = lo16 + 2u * lane;       s_bc[1] = S_lo - h2.x;
            }
        }
        __syncthreads();                         // barrier #3

        const unsigned t16sel = s_bc[0];
        const unsigned rem2   = remBand - s_bc[1];   // rank within crossing bin, >= 1

        // ---- collect crossing-bin candidates as packed keys ----
        #pragma unroll
        for (int j = 0; j < EPT; ++j) {
            if ((r[j] >> 16) == t16sel) {
                unsigned key = ((r[j] & 0xFFFFu) << 11) | (2047u - (idxBase + j));
                unsigned pos = atomicAdd(&s_n, 1u);
                if (pos < 64u) s_cand[pos] = key;
            }
        }
        __syncthreads();                         // barrier #4

        unsigned n = s_n;
        if (n <= 64u) {
            // ---- warp0: exact rank-(rem2) select among n distinct keys ----
            if (wid == 0) {
                unsigned k0 = (lane < (int)n)        ? s_cand[lane]      : 0u;
                unsigned k1 = ((unsigned)lane + 32u < n) ? s_cand[lane + 32] : 0u;
                unsigned r0 = 0, r1 = 0;
                unsigned nn = n < 32u ? n : 32u;
                for (unsigned i = 0; i < nn; ++i) {
                    unsigned b = __shfl_sync(FULLM, k0, i);
                    r0 += (b > k0); r1 += (b > k1);
                }
                if (n > 32u) {
                    unsigned n2 = n - 32u;
                    for (unsigned i = 0; i < n2; ++i) {
                        unsigned b = __shfl_sync(FULLM, k1, i);
                        r0 += (b > k0); r1 += (b > k1);
                    }
                }
                unsigned target = rem2 - 1u;
                if ((unsigned)lane < n && r0 == target) {
                    s_res[0] = (t16sel << 16) | (k0 >> 11);
                    s_res[1] = 2047u - (k0 & 0x7FFu);
                }
                if ((unsigned)lane + 32u < n && r1 == target) {
                    s_res[0] = (t16sel << 16) | (k1 >> 11);
                    s_res[1] = 2047u - (k1 & 0x7FFu);
                }
            }
            __syncthreads();                     // barrier #5
        } else {
            generic = true;                      // block-uniform
        }
    }

    if (generic) {
        // ---- fully generic exact path: 4-pass byte radix + boundary index ----
        __syncthreads();
        unsigned prefix = 0, remG = K_SEL;
        for (int pass = 0; pass < 4; ++pass) {
            const int shift = 24 - 8 * pass;
            const unsigned pmask = (pass == 0) ? 0u : (0xFFFFFFFFu << (shift + 8));
            s_hist[tid] = 0;
            __syncthreads();
            for (int j = 0; j < EPT; ++j)
                if ((r[j] & pmask) == prefix)
                    atomicAdd(&s_hist[(r[j] >> shift) & 255u], 1u);
            __syncthreads();
            unsigned h = s_hist[tid], v = h;
            for (int off = 1; off < 32; off <<= 1) {
                unsigned o = __shfl_down_sync(FULLM, v, off);
                if (lane + off < 32) v += o;
            }
            if (lane == 0) s_cnt[wid] = v;
            __syncthreads();
            unsigned addHi = 0;
            for (int w = 0; w < 8; ++w)
                if (w > wid) addHi += s_cnt[w];
            unsigned S = v + addHi;
            if (S >= remG && S - h < remG) { s_bc[0] = (unsigned)tid; s_bc[1] = S - h; }
            __syncthreads();
            prefix |= s_bc[0] << shift;
            remG   -= s_bc[1];
            __syncthreads();
        }
        // locate idxT: index of the remG-th equal-to-prefix element (ascending index)
        unsigned cnt = 0;
        for (int j = 0; j < EPT; ++j) cnt += (r[j] == prefix) ? 1u : 0u;
        unsigned iv = cnt;
        for (int off = 1; off < 32; off <<= 1) {
            unsigned o = __shfl_up_sync(FULLM, iv, off);
            if (lane >= off) iv += o;
        }
        if (lane == 31) s_cnt[wid] = iv;
        __syncthreads();
        unsigned wOff = 0;
        for (int w = 0; w < 8; ++w)
            if (w < wid) wOff += s_cnt[w];
        unsigned excl = wOff + iv - cnt;
        if (excl < remG && remG <= excl + cnt) {
            unsigned need = remG - excl, run = 0;
            for (int j = 0; j < EPT; ++j)
                if (r[j] == prefix && ++run == need) {
                    s_res[0] = prefix;
                    s_res[1] = idxBase + j;
                }
        }
        __syncthreads();
    }

    const unsigned T    = s_res[0];
    const unsigned idxT = s_res[1];

    // ---- wait for own cp.async data (thread-local smem; no block sync needed) ----
    asm volatile("cp.async.wait_group 0;" ::: "memory");

    float4* mp = reinterpret_cast<float4*>(out_masked + base) + (tid << 1);
    float4* ip = reinterpret_cast<float4*>(out_inv    + base) + (tid << 1);

    float4 d0 = s_dn[tid * 2];
    float4 d1 = s_dn[tid * 2 + 1];
    float4 n0 = s_dn[512 + tid * 2];
    float4 n1 = s_dn[512 + tid * 2 + 1];

    float dv[8] = {d0.x, d0.y, d0.z, d0.w, d1.x, d1.y, d1.z, d1.w};
    float nv[8] = {n0.x, n0.y, n0.z, n0.w, n1.x, n1.y, n1.z, n1.w};

    float ov[8], gv[8];
    #pragma unroll
    for (int j = 0; j < EPT; ++j) {
        bool masked = (r[j] > T) | ((r[j] == T) & (idxBase + (unsigned)j <= idxT));
        ov[j] = masked ? 0.0f : fmaf(0.1f, nv[j], dv[j]);
        gv[j] = masked ? 0.0f : 1.0f;
    }
    __stcs(mp,     make_float4(ov[0], ov[1], ov[2], ov[3]));
    __stcs(mp + 1, make_float4(ov[4], ov[5], ov[6], ov[7]));
    __stcs(ip,     make_float4(gv[0], gv[1], gv[2], gv[3]));
    __stcs(ip + 1, make_float4(gv[4], gv[5], gv[6], gv[7]));
}

extern "C" void kernel_launch(void* const* d_in, const int* in_sizes, int n_in,
                              void* d_out, int out_size)
{
    const float* data  = (const float*)d_in[0];
    const float* noise = (const float*)d_in[1];
    const float* rv    = (const float*)d_in[2];
    float* out = (float*)d_out;

    size_t n = (size_t)in_sizes[0];   // 32*1024*2048
    int rows = (int)(n / D_DIM);      // 32768

    obs_mask_kernel<<<rows, TPB>>>(data, noise, rv, out, out + n);
}

// round 8
// speedup vs baseline: 1.1620x; 1.0559x over previous
#include <cuda_runtime.h>
#include <cstdint>

// (32, 1024, 2048) fp32.  noisy = data + 0.1*noise; mask top-512 uniforms per row
// (ties at threshold -> lowest index first, matching jax.lax.top_k stability).
// out[0:N) = masked, out[N:2N) = mask_inverse.

#define D_DIM 2048
#define K_SEL 512
#define TPB   256
#define EPT   8          // D_DIM / TPB, contiguous per thread
#define FULLM 0xFFFFFFFFu

#define CP_ASYNC16(dst_u32, src_ptr) \
    asm volatile("cp.async.cg.shared.global [%0], [%1], 16;" :: "r"(dst_u32), "l"(src_ptr) : "memory")

__global__ __launch_bounds__(TPB, 8)
void obs_mask_kernel(const float* __restrict__ data,
                     const float* __restrict__ noise,
                     const float* __restrict__ rand_vals,
                     float* __restrict__ out_masked,
                     float* __restrict__ out_inv)
{
    __shared__ float4   s_dn[1024];    // 16KB: [0,512) = data row, [512,1024) = noise row
    __shared__ unsigned s_hist[256];   // fast path uses [0..63]; fallback uses all 256
    __shared__ unsigned s_cnt[8];
    __shared__ unsigned s_cand[64];
    __shared__ unsigned s_bc[2];       // {selected t16 bin, count strictly above bin}
    __shared__ unsigned s_res[2];      // {T bits, idxT}
    __shared__ unsigned s_n;

    const int tid  = threadIdx.x;
    const int lane = tid & 31;
    const int wid  = tid >> 5;
    const size_t base = (size_t)blockIdx.x * D_DIM;
    const unsigned idxBase = (unsigned)tid << 3;

    // ---- rand loads into registers (needed immediately for selection) ----
    const uint4* rp = reinterpret_cast<const uint4*>(rand_vals + base) + (tid << 1);
    uint4 ra = __ldcs(rp);
    uint4 rb = __ldcs(rp + 1);

    // ---- cp.async prefetch of data+noise into smem: drains during selection,
    //      costs no registers. Each thread copies (and later reads) its own bytes.
    {
        unsigned sbase = (unsigned)__cvta_generic_to_shared(s_dn);
        const float4* dp = reinterpret_cast<const float4*>(data  + base) + (tid << 1);
        const float4* np = reinterpret_cast<const float4*>(noise + base) + (tid << 1);
        unsigned dD = sbase + (unsigned)(tid * 32);            // 2 float4 per thread
        unsigned dN = sbase + 8192u + (unsigned)(tid * 32);
        CP_ASYNC16(dD,       dp);
        CP_ASYNC16(dD + 16u, dp + 1);
        CP_ASYNC16(dN,       np);
        CP_ASYNC16(dN + 16u, np + 1);
        asm volatile("cp.async.commit_group;" ::: "memory");
    }

    unsigned r[EPT] = {ra.x, ra.y, ra.z, ra.w, rb.x, rb.y, rb.z, rb.w};

    // ---- cheap exact band census: c1 = #{v>=0.75}, c2 = #{v>=0.5}, any >= 1.0 ----
    unsigned cpk = 0;   // c1 in low 16, c2 in high 16
    int big = 0;
    #pragma unroll
    for (int j = 0; j < EPT; ++j) {
        cpk += (r[j] >= 0x3F400000u) ? 1u : 0u;
        cpk += (r[j] >= 0x3F000000u) ? 0x10000u : 0u;
        big |= (r[j] >= 0x3F800000u);
    }
    #pragma unroll
    for (int off = 16; off >= 1; off >>= 1)
        cpk += __shfl_down_sync(FULLM, cpk, off);
    if (lane == 0) s_cnt[wid] = cpk;
    if (tid < 64) s_hist[tid] = 0;
    if (tid == 0) s_n = 0;

    int anyBig = __syncthreads_or(big);          // barrier #1

    unsigned csum = 0;
    #pragma unroll
    for (int w = 0; w < 8; ++w) csum += s_cnt[w];
    const unsigned c1 = csum & 0xFFFFu;
    const unsigned c2 = csum >> 16;

    bool generic = (anyBig != 0);
    unsigned lo16 = 0, remBand = 0;
    if (!generic) {
        if (c1 >= K_SEL)      { lo16 = 0x3F40u; remBand = K_SEL; }
        else if (c2 >= K_SEL) { lo16 = 0x3F00u; remBand = K_SEL - c1; }
        else                  { generic = true; }
    }

    if (!generic) {
        // ---- 64-bin histogram over the quarter-band only (~2 atomics/thread) ----
        #pragma unroll
        for (int j = 0; j < EPT; ++j) {
            unsigned bin = (r[j] >> 16) - lo16;
            if (bin < 64u) atomicAdd(&s_hist[bin], 1u);
        }
        __syncthreads();                         // barrier #2

        // ---- warp0: suffix scan of 64 bins, pick crossing bin ----
        if (wid == 0) {
            uint2 h2 = reinterpret_cast<const uint2*>(s_hist)[lane];  // bins 2l, 2l+1
            unsigned s1 = h2.y;
            unsigned s0 = h2.x + s1;
            unsigned inc = s0;
            #pragma unroll
            for (int off = 1; off < 32; off <<= 1) {
                unsigned o = __shfl_down_sync(FULLM, inc, off);
                if (lane + off < 32) inc += o;
            }
            unsigned abovePairs = inc - s0;
            unsigned S_hi = abovePairs + s1;      // bin 2l+1
            unsigned S_lo = abovePairs + s0;      // bin 2l
            if (S_hi >= remBand && S_hi - h2.y < remBand) {
                s_bc[0] = lo16 + 2u * lane + 1u;  s_bc[1] = S_hi - h2.y;
            }
            if (S_lo >= remBand && S_lo - h2.x < remBand) {
                s_bc[0] = lo16 + 2u * lane;       s_bc[1] = S_lo - h2.x;
            }
        }
        __syncthreads();                         // barrier #3

        const unsigned t16sel = s_bc[0];
        const unsigned rem2   = remBand - s_bc[1];   // rank within crossing bin, >= 1

        // ---- collect crossing-bin candidates as packed keys ----
        #pragma unroll
        for (int j = 0; j < EPT; ++j) {
            if ((r[j] >> 16) == t16sel) {
                unsigned key = ((r[j] & 0xFFFFu) << 11) | (2047u - (idxBase + j));
                unsigned pos = atomicAdd(&s_n, 1u);
                if (pos < 64u) s_cand[pos] = key;
            }
        }
        __syncthreads();                         // barrier #4

        unsigned n = s_n;
        if (n <= 64u) {
            // ---- warp0: exact rank-(rem2) select among n distinct keys ----
            if (wid == 0) {
                unsigned k0 = (lane < (int)n)        ? s_cand[lane]      : 0u;
                unsigned k1 = ((unsigned)lane + 32u < n) ? s_cand[lane + 32] : 0u;
                unsigned r0 = 0, r1 = 0;
                unsigned nn = n < 32u ? n : 32u;
                for (unsigned i = 0; i < nn; ++i) {
                    unsigned b = __shfl_sync(FULLM, k0, i);
                    r0 += (b > k0); r1 += (b > k1);
                }
                if (n > 32u) {
                    unsigned n2 = n - 32u;
                    for (unsigned i = 0; i < n2; ++i) {
                        unsigned b = __shfl_sync(FULLM, k1, i);
                        r0 += (b > k0); r1 += (b > k1);
                    }
                }
                unsigned target = rem2 - 1u;
                if ((unsigned)lane < n && r0 == target) {
                    s_res[0] = (t16sel << 16) | (k0 >> 11);
                    s_res[1] = 2047u - (k0 & 0x7FFu);
                }
                if ((unsigned)lane + 32u < n && r1 == target) {
                    s_res[0] = (t16sel << 16) | (k1 >> 11);
                    s_res[1] = 2047u - (k1 & 0x7FFu);
                }
            }
            __syncthreads();                     // barrier #5
        } else {
            generic = true;                      // block-uniform
        }
    }

    if (generic) {
        // ---- fully generic exact path: 4-pass byte radix + boundary index ----
        __syncthreads();
        unsigned prefix = 0, remG = K_SEL;
        for (int pass = 0; pass < 4; ++pass) {
            const int shift = 24 - 8 * pass;
            const unsigned pmask = (pass == 0) ? 0u : (0xFFFFFFFFu << (shift + 8));
            s_hist[tid] = 0;
            __syncthreads();
            for (int j = 0; j < EPT; ++j)
                if ((r[j] & pmask) == prefix)
                    atomicAdd(&s_hist[(r[j] >> shift) & 255u], 1u);
            __syncthreads();
            unsigned h = s_hist[tid], v = h;
            for (int off = 1; off < 32; off <<= 1) {
                unsigned o = __shfl_down_sync(FULLM, v, off);
                if (lane + off < 32) v += o;
            }
            if (lane == 0) s_cnt[wid] = v;
            __syncthreads();
            unsigned addHi = 0;
            for (int w = 0; w < 8; ++w)
                if (w > wid) addHi += s_cnt[w];
            unsigned S = v + addHi;
            if (S >= remG && S - h < remG) { s_bc[0] = (unsigned)tid; s_bc[1] = S - h; }
            __syncthreads();
            prefix |= s_bc[0] << shift;
            remG   -= s_bc[1];
            __syncthreads();
        }
        // locate idxT: index of the remG-th equal-to-prefix element (ascending index)
        unsigned cnt = 0;
        for (int j = 0; j < EPT; ++j) cnt += (r[j] == prefix) ? 1u : 0u;
        unsigned iv = cnt;
        for (int off = 1; off < 32; off <<= 1) {
            unsigned o = __shfl_up_sync(FULLM, iv, off);
            if (lane >= off) iv += o;
        }
        if (lane == 31) s_cnt[wid] = iv;
        __syncthreads();
        unsigned wOff = 0;
        for (int w = 0; w < 8; ++w)
            if (w < wid) wOff += s_cnt[w];
        unsigned excl = wOff + iv - cnt;
        if (excl < remG && remG <= excl + cnt) {
            unsigned need = remG - excl, run = 0;
            for (int j = 0; j < EPT; ++j)
                if (r[j] == prefix && ++run == need) {
                    s_res[0] = prefix;
                    s_res[1] = idxBase + j;
                }
        }
        __syncthreads();
    }

    const unsigned T    = s_res[0];
    const unsigned idxT = s_res[1];

    // ---- wait for own cp.async data (thread-local smem; no block sync needed) ----
    asm volatile("cp.async.wait_group 0;" ::: "memory");

    float4* mp = reinterpret_cast<float4*>(out_masked + base) + (tid << 1);
    float4* ip = reinterpret_cast<float4*>(out_inv    + base) + (tid << 1);

    // compute mask predicates first (frees r early, keeps live set small)
    bool mk[EPT];
    #pragma unroll
    for (int j = 0; j < EPT; ++j)
        mk[j] = (r[j] > T) | ((r[j] == T) & (idxBase + (unsigned)j <= idxT));

    __stcs(ip,     make_float4(mk[0] ? 0.f : 1.f, mk[1] ? 0.f : 1.f,
                               mk[2] ? 0.f : 1.f, mk[3] ? 0.f : 1.f));
    __stcs(ip + 1, make_float4(mk[4] ? 0.f : 1.f, mk[5] ? 0.f : 1.f,
                               mk[6] ? 0.f : 1.f, mk[7] ? 0.f : 1.f));

    {
        float4 d0 = s_dn[tid * 2];
        float4 n0 = s_dn[512 + tid * 2];
        __stcs(mp, make_float4(mk[0] ? 0.f : fmaf(0.1f, n0.x, d0.x),
                               mk[1] ? 0.f : fmaf(0.1f, n0.y, d0.y),
                               mk[2] ? 0.f : fmaf(0.1f, n0.z, d0.z),
                               mk[3] ? 0.f : fmaf(0.1f, n0.w, d0.w)));
    }
    {
        float4 d1 = s_dn[tid * 2 + 1];
        float4 n1 = s_dn[512 + tid * 2 + 1];
        __stcs(mp + 1, make_float4(mk[4] ? 0.f : fmaf(0.1f, n1.x, d1.x),
                                   mk[5] ? 0.f : fmaf(0.1f, n1.y, d1.y),
                                   mk[6] ? 0.f : fmaf(0.1f, n1.z, d1.z),
                                   mk[7] ? 0.f : fmaf(0.1f, n1.w, d1.w)));
    }
}

extern "C" void kernel_launch(void* const* d_in, const int* in_sizes, int n_in,
                              void* d_out, int out_size)
{
    const float* data  = (const float*)d_in[0];
    const float* noise = (const float*)d_in[1];
    const float* rv    = (const float*)d_in[2];
    float* out = (float*)d_out;

    size_t n = (size_t)in_sizes[0];   // 32*1024*2048
    int rows = (int)(n / D_DIM);      // 32768

    obs_mask_kernel<<<rows, TPB>>>(data, noise, rv, out, out + n);
}